// round 1
// baseline (speedup 1.0000x reference)
#include <cuda_runtime.h>
#include <math.h>

#define Bb   2
#define Hh   192
#define Wd   192
#define VD_  384
#define CD_  128
#define ID_  384
#define NH_  8
#define HD_  48
#define WS_  8
#define NW_  24
#define NTOK (Bb*Hh*Wd)   // 73728

// ---------------- scratch (device globals; no runtime alloc allowed) --------
__device__ float g_pv[(size_t)NTOK * 1152];                       // raw vqk(768) | vv(384)
__device__ float g_pc[(size_t)NTOK * 768];                        // raw cqk
__device__ float g_QF[(size_t)Bb*NH_*NW_*NW_*64*96];              // [qv(48) | lambda*qc(48)]
__device__ float g_KF[(size_t)Bb*NH_*NW_*NW_*64*96];              // [kv(48) | kc(48)]
__device__ float g_VB[(size_t)Bb*NH_*NW_*NW_*64*48];
__device__ float g_Y [(size_t)NTOK * ID_];

// ---------------- generic 64x64-tile SGEMM:  C = A[M,K] @ W[K,N] + bias -----
__global__ __launch_bounds__(256) void sgemm64(
    const float* __restrict__ A, const float* __restrict__ Wt,
    const float* __restrict__ bias, float* __restrict__ C,
    int K, int N, int ldc)
{
    __shared__ float As[16][64];
    __shared__ float Bs[16][64];
    const int tid = threadIdx.x;
    const int n0 = blockIdx.x * 64;
    const int m0 = blockIdx.y * 64;
    const int ty = tid >> 4, tx = tid & 15;
    const int ar = tid >> 2, ac = (tid & 3) << 2;   // A tile load: 64 rows x 16 k
    const int br = tid >> 4, bc = (tid & 15) << 2;  // B tile load: 16 k x 64 n

    float acc[4][4] = {};
    for (int kk = 0; kk < K; kk += 16) {
        float4 av = *(const float4*)(A + (size_t)(m0 + ar) * K + kk + ac);
        As[ac + 0][ar] = av.x; As[ac + 1][ar] = av.y;
        As[ac + 2][ar] = av.z; As[ac + 3][ar] = av.w;
        *(float4*)&Bs[br][bc] = *(const float4*)(Wt + (size_t)(kk + br) * N + n0 + bc);
        __syncthreads();
#pragma unroll
        for (int k = 0; k < 16; k++) {
            float4 a = *(const float4*)&As[k][ty << 2];
            float4 b = *(const float4*)&Bs[k][tx << 2];
            float aa[4] = {a.x, a.y, a.z, a.w};
            float bb[4] = {b.x, b.y, b.z, b.w};
#pragma unroll
            for (int i = 0; i < 4; i++)
#pragma unroll
                for (int j = 0; j < 4; j++)
                    acc[i][j] += aa[i] * bb[j];
        }
        __syncthreads();
    }
#pragma unroll
    for (int i = 0; i < 4; i++) {
        int m = m0 + (ty << 2) + i;
#pragma unroll
        for (int j = 0; j < 4; j++) {
            int n = n0 + (tx << 2) + j;
            C[(size_t)m * ldc + n] = acc[i][j] + bias[n];
        }
    }
}

// ------------- RMSNorm + interleaved split + roll + window scatter ----------
__global__ __launch_bounds__(128) void scatter_k(
    const float* __restrict__ gvqk, const float* __restrict__ gcqk,
    const float* __restrict__ lamp)
{
    __shared__ float sv[1152];
    __shared__ float sc[768];
    __shared__ float wsum[8];
    const int p = blockIdx.x;
    const int tid = threadIdx.x;
    const float* pv = g_pv + (size_t)p * 1152;
    const float* pc = g_pc + (size_t)p * 768;
    for (int i = tid; i < 1152; i += 128) sv[i] = pv[i];
    for (int i = tid; i < 768;  i += 128) sc[i] = pc[i];
    __syncthreads();

    float s1 = 0.f, s2 = 0.f;
    for (int i = tid; i < 768; i += 128) {
        float a = sv[i]; s1 += a * a;
        float c = sc[i]; s2 += c * c;
    }
#pragma unroll
    for (int o = 16; o; o >>= 1) {
        s1 += __shfl_xor_sync(0xffffffffu, s1, o);
        s2 += __shfl_xor_sync(0xffffffffu, s2, o);
    }
    if ((tid & 31) == 0) { wsum[tid >> 5] = s1; wsum[4 + (tid >> 5)] = s2; }
    __syncthreads();
    const float S1 = wsum[0] + wsum[1] + wsum[2] + wsum[3];
    const float S2 = wsum[4] + wsum[5] + wsum[6] + wsum[7];
    const float r1 = rsqrtf(S1 * (1.f / 768.f) + 1e-6f);
    const float r2 = rsqrtf(S2 * (1.f / 768.f) + 1e-6f);
    const float lam = lamp[0];

    const int b = p / (Hh * Wd);
    const int rem = p - b * (Hh * Wd);
    const int y = rem / Wd, x = rem - (rem / Wd) * Wd;
    // roll(-4): rolled[yr] = src[(yr+4)%H]  =>  src (y,x) lands at ((y-4)%H,(x-4)%W)
    const int yr = (y + Hh - 4) % Hh, xr = (x + Wd - 4) % Wd;
    const int wy = yr >> 3, wx = xr >> 3;
    const int tok = ((yr & 7) << 3) | (xr & 7);

    for (int d = tid; d < 384; d += 128) {
        const int head = d & 7, e = d >> 3;           // feature layout (e H): head fast
        const size_t wbase = ((((size_t)b * NH_ + head) * NW_ + wy) * NW_ + wx) * 64 + tok;
        float q = sv[3 * d], k = sv[3 * d + 1], v = sv[3 * d + 2];
        if (d < 256) {                                 // channels <768: normed vqk
            q *= r1 * gvqk[3 * d];
            k *= r1 * gvqk[3 * d + 1];
            v *= r1 * gvqk[3 * d + 2];
        }
        const float qc = sc[2 * d]     * r2 * gcqk[2 * d] * lam;
        const float kc = sc[2 * d + 1] * r2 * gcqk[2 * d + 1];
        g_QF[wbase * 96 + e]      = q;
        g_QF[wbase * 96 + 48 + e] = qc;
        g_KF[wbase * 96 + e]      = k;
        g_KF[wbase * 96 + 48 + e] = kc;
        g_VB[wbase * 48 + e]      = v;
    }
}

// ---------------------------- windowed attention ----------------------------
#define QSTR 97   // smem row stride (odd -> conflict-poor scalar access)

__global__ __launch_bounds__(256) void attn_k(const float* __restrict__ pos_emb)
{
    extern __shared__ float sm[];
    float* Qs = sm;                 // 64*97
    float* Ks = sm + 64 * QSTR;     // 64*97
    float* Vs = Ks + 64 * QSTR;     // 64*48
    float* Ds = Vs + 64 * 48;       // 64*65
    float* Ps = Ds + 64 * 65;       // 225

    int blk = blockIdx.x;
    const int wx = blk % NW_; blk /= NW_;
    const int wy = blk % NW_; blk /= NW_;
    const int head = blk % NH_;
    const int b = blk / NH_;
    const int tid = threadIdx.x;

    const size_t wbase = ((((size_t)b * NH_ + head) * NW_ + wy) * NW_ + wx) * 64;
    const float* qg = g_QF + wbase * 96;
    const float* kg = g_KF + wbase * 96;
    const float* vg = g_VB + wbase * 48;

    for (int i = tid; i < 64 * 96; i += 256) {
        const int t0 = i / 96, e = i - t0 * 96;
        Qs[t0 * QSTR + e] = qg[i];
        Ks[t0 * QSTR + e] = kg[i];
    }
    for (int i = tid; i < 64 * 48 / 4; i += 256)
        *(float4*)&Vs[i * 4] = ((const float4*)vg)[i];
    for (int i = tid; i < 225; i += 256) Ps[i] = pos_emb[i];
    __syncthreads();

    // ---- dots: 16x16 threads, 4x4 micro-tile, 96-dim fused dot ----
    const int ty = tid >> 4, tx = tid & 15;
    float acc[4][4] = {};
#pragma unroll 4
    for (int e = 0; e < 96; e++) {
        float q0 = Qs[(ty * 4 + 0) * QSTR + e];
        float q1 = Qs[(ty * 4 + 1) * QSTR + e];
        float q2 = Qs[(ty * 4 + 2) * QSTR + e];
        float q3 = Qs[(ty * 4 + 3) * QSTR + e];
        float k0 = Ks[(tx * 4 + 0) * QSTR + e];
        float k1 = Ks[(tx * 4 + 1) * QSTR + e];
        float k2 = Ks[(tx * 4 + 2) * QSTR + e];
        float k3 = Ks[(tx * 4 + 3) * QSTR + e];
        acc[0][0] += q0 * k0; acc[0][1] += q0 * k1; acc[0][2] += q0 * k2; acc[0][3] += q0 * k3;
        acc[1][0] += q1 * k0; acc[1][1] += q1 * k1; acc[1][2] += q1 * k2; acc[1][3] += q1 * k3;
        acc[2][0] += q2 * k0; acc[2][1] += q2 * k1; acc[2][2] += q2 * k2; acc[2][3] += q2 * k3;
        acc[3][0] += q3 * k0; acc[3][1] += q3 * k1; acc[3][2] += q3 * k2; acc[3][3] += q3 * k3;
    }
    const float scale = 0.14433756729740643f;   // 1/sqrt(48)
    const bool lastR = (wy == NW_ - 1), lastC = (wx == NW_ - 1);
#pragma unroll
    for (int i4 = 0; i4 < 4; i4++) {
        const int i = ty * 4 + i4;
#pragma unroll
        for (int j4 = 0; j4 < 4; j4++) {
            const int j = tx * 4 + j4;
            float v = acc[i4][j4] * scale
                    + Ps[((j >> 3) - (i >> 3) + 7) * 15 + ((j & 7) - (i & 7) + 7)];
            if (lastR && (((i >= 32) ? 1 : 0) ^ ((j >= 32) ? 1 : 0)))          v = -INFINITY;
            if (lastC && ((((i & 7) >= 4) ? 1 : 0) ^ (((j & 7) >= 4) ? 1 : 0))) v = -INFINITY;
            Ds[i * 65 + j] = v;
        }
    }
    __syncthreads();

    // ---- softmax: 4 threads per row ----
    const int r = tid >> 2, qd = tid & 3;
    float m = -INFINITY;
#pragma unroll
    for (int j = 0; j < 16; j++) m = fmaxf(m, Ds[r * 65 + qd * 16 + j]);
    m = fmaxf(m, __shfl_xor_sync(0xffffffffu, m, 1));
    m = fmaxf(m, __shfl_xor_sync(0xffffffffu, m, 2));
    float s = 0.f;
#pragma unroll
    for (int j = 0; j < 16; j++) {
        float eV = __expf(Ds[r * 65 + qd * 16 + j] - m);
        Ds[r * 65 + qd * 16 + j] = eV;
        s += eV;
    }
    s += __shfl_xor_sync(0xffffffffu, s, 1);
    s += __shfl_xor_sync(0xffffffffu, s, 2);
    const float inv = 1.f / s;
    __syncthreads();

    // ---- AV: thread owns (row r, 12 e's) ----
    float o[12] = {};
    for (int j = 0; j < 64; j++) {
        const float a = Ds[r * 65 + j] * inv;
        const float* vp = &Vs[j * 48 + qd * 12];
#pragma unroll
        for (int u = 0; u < 3; u++) {
            float4 v4 = *(const float4*)&vp[u * 4];
            o[u * 4 + 0] += a * v4.x; o[u * 4 + 1] += a * v4.y;
            o[u * 4 + 2] += a * v4.z; o[u * 4 + 3] += a * v4.w;
        }
    }
    // output layout: no roll-back; channel = head*HD + e (heads slow)
    const int Y = wy * 8 + (r >> 3), X = wx * 8 + (r & 7);
    float* op = g_Y + (((size_t)b * Hh + Y) * Wd + X) * ID_ + head * HD_ + qd * 12;
#pragma unroll
    for (int u = 0; u < 3; u++)
        *(float4*)&op[u * 4] = make_float4(o[u*4], o[u*4+1], o[u*4+2], o[u*4+3]);
}

// ------------------------------- launcher -----------------------------------
extern "C" void kernel_launch(void* const* d_in, const int* in_sizes, int n_in,
                              void* d_out, int out_size)
{
    const float* values = (const float*)d_in[0];
    const float* coords = (const float*)d_in[1];
    const float* W_vqk  = (const float*)d_in[2];
    const float* b_vqk  = (const float*)d_in[3];
    const float* gm_vqk = (const float*)d_in[4];
    const float* W_vv   = (const float*)d_in[5];
    const float* b_vv   = (const float*)d_in[6];
    const float* W_cqk  = (const float*)d_in[7];
    const float* b_cqk  = (const float*)d_in[8];
    const float* gm_cqk = (const float*)d_in[9];
    const float* lam    = (const float*)d_in[10];
    const float* pos    = (const float*)d_in[11];
    const float* W_ov   = (const float*)d_in[12];
    const float* b_ov   = (const float*)d_in[13];
    float* out = (float*)d_out;

    float *pv, *pc, *yb;
    cudaGetSymbolAddress((void**)&pv, g_pv);
    cudaGetSymbolAddress((void**)&pc, g_pc);
    cudaGetSymbolAddress((void**)&yb, g_Y);

    // projections (fused vqk|vv into one 1152-wide row buffer)
    sgemm64<<<dim3(768 / 64, NTOK / 64), 256>>>(values, W_vqk, b_vqk, pv,        384, 768, 1152);
    sgemm64<<<dim3(384 / 64, NTOK / 64), 256>>>(values, W_vv,  b_vv,  pv + 768,  384, 384, 1152);
    sgemm64<<<dim3(768 / 64, NTOK / 64), 256>>>(coords, W_cqk, b_cqk, pc,        128, 768, 768);

    // rmsnorm + interleaved q/k/v split + roll + window layout
    scatter_k<<<NTOK, 128>>>(gm_vqk, gm_cqk, lam);

    // attention
    const int smem = (64 * QSTR * 2 + 64 * 48 + 64 * 65 + 225) * (int)sizeof(float);
    cudaFuncSetAttribute(attn_k, cudaFuncAttributeMaxDynamicSharedMemorySize, smem);
    attn_k<<<Bb * NH_ * NW_ * NW_, 256, smem>>>(pos);

    // output projection
    sgemm64<<<dim3(384 / 64, NTOK / 64), 256>>>(yb, W_ov, b_ov, out, 384, 384, 384);
}

// round 3
// speedup vs baseline: 1.5592x; 1.5592x over previous
#include <cuda_runtime.h>
#include <cuda_bf16.h>
#include <math.h>
#include <stdint.h>

#define Bb   2
#define Hh   192
#define Wd   192
#define NH_  8
#define HD_  48
#define NW_  24
#define NTOK (Bb*Hh*Wd)   // 73728

// ---------------- scratch (device globals; no runtime alloc) ----------------
__device__ __nv_bfloat16 g_Av[(size_t)NTOK * 1152];   // values split [hi|hi|lo]
__device__ __nv_bfloat16 g_Ac[(size_t)NTOK * 384];    // coords split
__device__ __nv_bfloat16 g_Yb[(size_t)NTOK * 1152];   // attn out split
__device__ __nv_bfloat16 g_Bv[1152 * 1152];           // W' combined vqk|vv  [N,K']
__device__ __nv_bfloat16 g_Bc[768 * 384];             // W' cqk
__device__ __nv_bfloat16 g_Bo[384 * 1152];             // W' ov
__device__ float g_biasv[1152];
__device__ float g_pv[(size_t)NTOK * 1152];           // raw vqk(768)|vv(384)
__device__ float g_pc[(size_t)NTOK * 768];            // raw cqk
__device__ float g_QF[(size_t)NTOK * NH_ * 96];       // [qv(48)|lam*qc(48)]
__device__ float g_KF[(size_t)NTOK * NH_ * 96];
__device__ float g_VB[(size_t)NTOK * NH_ * 48];

// ------------------------------ PTX helpers ---------------------------------
__device__ __forceinline__ uint32_t s2u(const void* p) {
    uint32_t a;
    asm("{ .reg .u64 t; cvta.to.shared.u64 t, %1; cvt.u32.u64 %0, t; }" : "=r"(a) : "l"(p));
    return a;
}
__device__ __forceinline__ void cp16(uint32_t dst, const void* src) {
    asm volatile("cp.async.cg.shared.global [%0], [%1], 16;" :: "r"(dst), "l"(src));
}
#define CP_COMMIT() asm volatile("cp.async.commit_group;" ::: "memory")
#define CP_WAIT1()  asm volatile("cp.async.wait_group 1;" ::: "memory")
#define CP_WAIT0()  asm volatile("cp.async.wait_group 0;" ::: "memory")

#define LDSM4(R0,R1,R2,R3,ADDR) \
    asm volatile("ldmatrix.sync.aligned.m8n8.x4.shared.b16 {%0,%1,%2,%3}, [%4];" \
                 : "=r"(R0), "=r"(R1), "=r"(R2), "=r"(R3) : "r"(ADDR))

#define MMA16816(D,A0,A1,A2,A3,B0,B1) \
    asm volatile("mma.sync.aligned.m16n8k16.row.col.f32.bf16.bf16.f32 " \
                 "{%0,%1,%2,%3},{%4,%5,%6,%7},{%8,%9},{%0,%1,%2,%3};" \
                 : "+f"(D[0]), "+f"(D[1]), "+f"(D[2]), "+f"(D[3]) \
                 : "r"(A0), "r"(A1), "r"(A2), "r"(A3), "r"(B0), "r"(B1))

// ------------------------------ pack kernels --------------------------------
__global__ void pack_A(const float* __restrict__ X, __nv_bfloat16* __restrict__ O, int K) {
    size_t i = (size_t)blockIdx.x * 256 + threadIdx.x;
    if (i >= (size_t)NTOK * K) return;
    size_t t = i / K; int k = (int)(i - t * K);
    float x = X[i];
    __nv_bfloat16 hi = __float2bfloat16(x);
    __nv_bfloat16 lo = __float2bfloat16(x - __bfloat162float(hi));
    __nv_bfloat16* row = O + t * (size_t)(3 * K);
    row[k] = hi; row[K + k] = hi; row[2 * K + k] = lo;
}
__global__ void pack_Bv(const float* __restrict__ Wqk, const float* __restrict__ Wvv,
                        __nv_bfloat16* __restrict__ O) {                 // K=384, N=1152
    int i = blockIdx.x * 256 + threadIdx.x;
    if (i >= 1152 * 384) return;
    int n = i / 384, k = i - (i / 384) * 384;
    float w = (n < 768) ? Wqk[(size_t)k * 768 + n] : Wvv[(size_t)k * 384 + (n - 768)];
    __nv_bfloat16 hi = __float2bfloat16(w);
    __nv_bfloat16 lo = __float2bfloat16(w - __bfloat162float(hi));
    __nv_bfloat16* row = O + (size_t)n * 1152;
    row[k] = hi; row[384 + k] = lo; row[768 + k] = hi;
}
__global__ void pack_B(const float* __restrict__ W, __nv_bfloat16* __restrict__ O,
                       int K, int N) {                                   // W is [K,N]
    int i = blockIdx.x * 256 + threadIdx.x;
    if (i >= N * K) return;
    int n = i / K, k = i - (i / K) * K;
    float w = W[(size_t)k * N + n];
    __nv_bfloat16 hi = __float2bfloat16(w);
    __nv_bfloat16 lo = __float2bfloat16(w - __bfloat162float(hi));
    __nv_bfloat16* row = O + (size_t)n * (3 * K);
    row[k] = hi; row[K + k] = lo; row[2 * K + k] = hi;
}
__global__ void bias_cat(const float* __restrict__ a, const float* __restrict__ b) {
    int i = blockIdx.x * 256 + threadIdx.x;
    if (i < 1152) g_biasv[i] = (i < 768) ? a[i] : b[i - 768];
}

// --------- HMMA GEMM: C[M,N] = A'[M,K'] @ B'[N,K']^T + bias -----------------
// CTA tile 128x128, 8 warps (4 m-slices x 2 n-slices), warp tile 32x64.
// K chunked by 64 bf16 (128B SW128 rows), cp.async double-buffered.
// smem: A0 @0, A1 @16K, B0 @32K, B1 @48K  (total 64KB dynamic)
__global__ __launch_bounds__(256, 1) void gemm_mma(
    const __nv_bfloat16* __restrict__ A, const __nv_bfloat16* __restrict__ B,
    const float* __restrict__ bias, float* __restrict__ C, int Kp, int ldc)
{
    extern __shared__ __align__(1024) char smem[];
    const uint32_t sb = s2u(smem);
    const int tid = threadIdx.x, lane = tid & 31, wid = tid >> 5;
    const int m0 = blockIdx.y * 128, n0 = blockIdx.x * 128;
    const int wm = (wid & 3) << 5;       // warp m offset (32)
    const int wn = (wid >> 2) << 6;      // warp n offset (64)

    // ---- global->smem load geometry: each thread moves 4x16B for A and B
    const int lrow = tid >> 3, lu = tid & 7;          // 32 rows x 8 cols16 per pass
    const size_t ldk = (size_t)Kp * 2;
    const char* Asrc = (const char*)A + (size_t)(m0 + lrow) * ldk + lu * 16;
    const char* Bsrc = (const char*)B + (size_t)(n0 + lrow) * ldk + lu * 16;
    uint32_t dsto[4];
#pragma unroll
    for (int r = 0; r < 4; r++) {
        const int row = lrow + r * 32;
        dsto[r] = row * 128 + ((lu ^ (row & 7)) << 4);
    }

    // ---- ldmatrix address geometry
    const int q  = lane >> 3, tr = lane & 7;
    const int qvA = q >> 1;                  // A: col16 half select
    const int qbB = q & 1;                   // B: col16 half select
    uint32_t rowoffA[2], xrA[2];
#pragma unroll
    for (int fm = 0; fm < 2; fm++) {
        const int row = wm + fm * 16 + tr + ((q & 1) << 3);
        rowoffA[fm] = row * 128; xrA[fm] = row & 7;
    }
    uint32_t rowoffB[4], xrB[4];
#pragma unroll
    for (int fn = 0; fn < 4; fn++) {
        const int row = wn + fn * 16 + tr + ((q >> 1) << 3);
        rowoffB[fn] = row * 128; xrB[fn] = row & 7;
    }

    float acc[2][8][4] = {};

    const int NC = Kp >> 6;
    // prefetch chunk 0 into buf 0
#pragma unroll
    for (int r = 0; r < 4; r++) {
        cp16(sb + dsto[r],          Asrc + r * 32 * ldk);
        cp16(sb + 32768u + dsto[r], Bsrc + r * 32 * ldk);
    }
    CP_COMMIT();

    for (int c = 0; c < NC; c++) {
        const int buf = c & 1;
        if (c + 1 < NC) {
            const uint32_t ab = sb + (buf ^ 1) * 16384u;
            const uint32_t bb = sb + 32768u + (buf ^ 1) * 16384u;
            const char* Ac_ = Asrc + (size_t)(c + 1) * 128;
            const char* Bc_ = Bsrc + (size_t)(c + 1) * 128;
#pragma unroll
            for (int r = 0; r < 4; r++) {
                cp16(ab + dsto[r], Ac_ + r * 32 * ldk);
                cp16(bb + dsto[r], Bc_ + r * 32 * ldk);
            }
            CP_COMMIT();
            CP_WAIT1();
        } else {
            CP_WAIT0();
        }
        __syncthreads();

        const uint32_t Ab = sb + buf * 16384u;
        const uint32_t Bs = sb + 32768u + buf * 16384u;
#pragma unroll
        for (int ks = 0; ks < 4; ks++) {
            uint32_t a[2][4], bf[4][4];
#pragma unroll
            for (int fm = 0; fm < 2; fm++) {
                const uint32_t ad = Ab + rowoffA[fm] + ((((uint32_t)(ks * 2 + qvA)) ^ xrA[fm]) << 4);
                LDSM4(a[fm][0], a[fm][1], a[fm][2], a[fm][3], ad);
            }
#pragma unroll
            for (int fn = 0; fn < 4; fn++) {
                const uint32_t bd = Bs + rowoffB[fn] + ((((uint32_t)(ks * 2 + qbB)) ^ xrB[fn]) << 4);
                LDSM4(bf[fn][0], bf[fn][1], bf[fn][2], bf[fn][3], bd);
            }
#pragma unroll
            for (int fm = 0; fm < 2; fm++)
#pragma unroll
                for (int fn = 0; fn < 4; fn++) {
                    MMA16816(acc[fm][2 * fn],     a[fm][0], a[fm][1], a[fm][2], a[fm][3],
                             bf[fn][0], bf[fn][1]);
                    MMA16816(acc[fm][2 * fn + 1], a[fm][0], a[fm][1], a[fm][2], a[fm][3],
                             bf[fn][2], bf[fn][3]);
                }
        }
        __syncthreads();
    }

    // ---- epilogue: acc + bias -> C
    const int er = lane >> 2, ec = (lane & 3) << 1;
#pragma unroll
    for (int fm = 0; fm < 2; fm++) {
#pragma unroll
        for (int fn = 0; fn < 8; fn++) {
            const int gm = m0 + wm + fm * 16 + er;
            const int gn = n0 + wn + fn * 8 + ec;
            const float2 bv = *(const float2*)(bias + gn);
            float2 o0, o1;
            o0.x = acc[fm][fn][0] + bv.x; o0.y = acc[fm][fn][1] + bv.y;
            o1.x = acc[fm][fn][2] + bv.x; o1.y = acc[fm][fn][3] + bv.y;
            *(float2*)(C + (size_t)gm * ldc + gn) = o0;
            *(float2*)(C + (size_t)(gm + 8) * ldc + gn) = o1;
        }
    }
}

// ------------- RMSNorm + interleaved split + roll + window scatter ----------
__global__ __launch_bounds__(256) void scatter_k(
    const float* __restrict__ gvqk, const float* __restrict__ gcqk,
    const float* __restrict__ lamp)
{
    __shared__ float sv[1152];
    __shared__ float sc[768];
    __shared__ float red[16];
    const int p = blockIdx.x, tid = threadIdx.x;
    const float* pv = g_pv + (size_t)p * 1152;
    const float* pc = g_pc + (size_t)p * 768;
    for (int i = tid; i < 1152; i += 256) sv[i] = pv[i];
    for (int i = tid; i < 768;  i += 256) sc[i] = pc[i];
    __syncthreads();

    float s1 = 0.f, s2 = 0.f;
    for (int i = tid; i < 768; i += 256) {
        float a = sv[i]; s1 += a * a;
        float c = sc[i]; s2 += c * c;
    }
#pragma unroll
    for (int o = 16; o; o >>= 1) {
        s1 += __shfl_xor_sync(0xffffffffu, s1, o);
        s2 += __shfl_xor_sync(0xffffffffu, s2, o);
    }
    if ((tid & 31) == 0) { red[tid >> 5] = s1; red[8 + (tid >> 5)] = s2; }
    __syncthreads();
    float S1 = 0.f, S2 = 0.f;
#pragma unroll
    for (int i = 0; i < 8; i++) { S1 += red[i]; S2 += red[8 + i]; }
    const float r1 = rsqrtf(S1 * (1.f / 768.f) + 1e-6f);
    const float r2 = rsqrtf(S2 * (1.f / 768.f) + 1e-6f);
    const float lam = lamp[0];

    const int b = p / (Hh * Wd);
    const int rem = p - b * (Hh * Wd);
    const int y = rem / Wd, x = rem - (rem / Wd) * Wd;
    const int yr = (y + Hh - 4) % Hh, xr = (x + Wd - 4) % Wd;
    const int wy = yr >> 3, wx = xr >> 3;
    const int tok = ((yr & 7) << 3) | (xr & 7);

    const int head = tid >> 5, lane = tid & 31;
    const size_t wbase = ((((size_t)b * NH_ + head) * NW_ + wy) * NW_ + wx) * 64 + tok;
    float* QFp = g_QF + wbase * 96;
    float* KFp = g_KF + wbase * 96;
    float* VBp = g_VB + wbase * 48;

#pragma unroll
    for (int jj = 0; jj < 3; jj++) {
        const int j = lane + jj * 32;
        float qv_, kv_;
        if (j < 48) {
            const int d = j * 8 + head;
            qv_ = sv[3 * d]; kv_ = sv[3 * d + 1];
            if (d < 256) { qv_ *= r1 * gvqk[3 * d]; kv_ *= r1 * gvqk[3 * d + 1]; }
        } else {
            const int d = (j - 48) * 8 + head;
            qv_ = sc[2 * d]     * r2 * gcqk[2 * d] * lam;
            kv_ = sc[2 * d + 1] * r2 * gcqk[2 * d + 1];
        }
        QFp[j] = qv_; KFp[j] = kv_;
    }
    {
        const int d = lane * 8 + head;
        float v = sv[3 * d + 2];
        if (d < 256) v *= r1 * gvqk[3 * d + 2];
        VBp[lane] = v;
        if (lane < 16) {
            const int d2 = (lane + 32) * 8 + head;
            VBp[lane + 32] = sv[3 * d2 + 2];   // d2 >= 256 always: raw
        }
    }
}

// ---------------------------- windowed attention ----------------------------
#define QSTR 97

__global__ __launch_bounds__(256) void attn_k(const float* __restrict__ pos_emb)
{
    extern __shared__ float sm[];
    float* Qs = sm;
    float* Ks = sm + 64 * QSTR;
    float* Vs = Ks + 64 * QSTR;
    float* Ds = Vs + 64 * 48;
    float* Ps = Ds + 64 * 65;

    int blk = blockIdx.x;
    const int wx = blk % NW_; blk /= NW_;
    const int wy = blk % NW_; blk /= NW_;
    const int head = blk % NH_;
    const int b = blk / NH_;
    const int tid = threadIdx.x;

    const size_t wbase = ((((size_t)b * NH_ + head) * NW_ + wy) * NW_ + wx) * 64;
    const float* qg = g_QF + wbase * 96;
    const float* kg = g_KF + wbase * 96;
    const float* vg = g_VB + wbase * 48;

    for (int i = tid; i < 64 * 96; i += 256) {
        const int t0 = i / 96, e = i - t0 * 96;
        Qs[t0 * QSTR + e] = qg[i];
        Ks[t0 * QSTR + e] = kg[i];
    }
    for (int i = tid; i < 64 * 48 / 4; i += 256)
        *(float4*)&Vs[i * 4] = ((const float4*)vg)[i];
    for (int i = tid; i < 225; i += 256) Ps[i] = pos_emb[i];
    __syncthreads();

    const int ty = tid >> 4, tx = tid & 15;
    float acc[4][4] = {};
#pragma unroll 4
    for (int e = 0; e < 96; e++) {
        float q0 = Qs[(ty * 4 + 0) * QSTR + e];
        float q1 = Qs[(ty * 4 + 1) * QSTR + e];
        float q2 = Qs[(ty * 4 + 2) * QSTR + e];
        float q3 = Qs[(ty * 4 + 3) * QSTR + e];
        float k0 = Ks[(tx * 4 + 0) * QSTR + e];
        float k1 = Ks[(tx * 4 + 1) * QSTR + e];
        float k2 = Ks[(tx * 4 + 2) * QSTR + e];
        float k3 = Ks[(tx * 4 + 3) * QSTR + e];
        acc[0][0] += q0 * k0; acc[0][1] += q0 * k1; acc[0][2] += q0 * k2; acc[0][3] += q0 * k3;
        acc[1][0] += q1 * k0; acc[1][1] += q1 * k1; acc[1][2] += q1 * k2; acc[1][3] += q1 * k3;
        acc[2][0] += q2 * k0; acc[2][1] += q2 * k1; acc[2][2] += q2 * k2; acc[2][3] += q2 * k3;
        acc[3][0] += q3 * k0; acc[3][1] += q3 * k1; acc[3][2] += q3 * k2; acc[3][3] += q3 * k3;
    }
    const float scale = 0.14433756729740643f;   // 1/sqrt(48)
    const bool lastR = (wy == NW_ - 1), lastC = (wx == NW_ - 1);
#pragma unroll
    for (int i4 = 0; i4 < 4; i4++) {
        const int i = ty * 4 + i4;
#pragma unroll
        for (int j4 = 0; j4 < 4; j4++) {
            const int j = tx * 4 + j4;
            float v = acc[i4][j4] * scale
                    + Ps[((j >> 3) - (i >> 3) + 7) * 15 + ((j & 7) - (i & 7) + 7)];
            if (lastR && (((i >= 32) ? 1 : 0) ^ ((j >= 32) ? 1 : 0)))           v = -INFINITY;
            if (lastC && ((((i & 7) >= 4) ? 1 : 0) ^ (((j & 7) >= 4) ? 1 : 0))) v = -INFINITY;
            Ds[i * 65 + j] = v;
        }
    }
    __syncthreads();

    const int r = tid >> 2, qd = tid & 3;
    float m = -INFINITY;
#pragma unroll
    for (int j = 0; j < 16; j++) m = fmaxf(m, Ds[r * 65 + qd * 16 + j]);
    m = fmaxf(m, __shfl_xor_sync(0xffffffffu, m, 1));
    m = fmaxf(m, __shfl_xor_sync(0xffffffffu, m, 2));
    float s = 0.f;
#pragma unroll
    for (int j = 0; j < 16; j++) {
        float eV = __expf(Ds[r * 65 + qd * 16 + j] - m);
        Ds[r * 65 + qd * 16 + j] = eV;
        s += eV;
    }
    s += __shfl_xor_sync(0xffffffffu, s, 1);
    s += __shfl_xor_sync(0xffffffffu, s, 2);
    const float inv = 1.f / s;
    __syncthreads();

    float o[12] = {};
    for (int j = 0; j < 64; j++) {
        const float a = Ds[r * 65 + j] * inv;
        const float* vp = &Vs[j * 48 + qd * 12];
#pragma unroll
        for (int u = 0; u < 3; u++) {
            float4 v4 = *(const float4*)&vp[u * 4];
            o[u * 4 + 0] += a * v4.x; o[u * 4 + 1] += a * v4.y;
            o[u * 4 + 2] += a * v4.z; o[u * 4 + 3] += a * v4.w;
        }
    }
    const int Y = wy * 8 + (r >> 3), X = wx * 8 + (r & 7);
    const size_t t = ((size_t)b * Hh + Y) * Wd + X;
    __nv_bfloat16* op = g_Yb + t * 1152 + head * HD_ + qd * 12;
#pragma unroll
    for (int u = 0; u < 12; u++) {
        __nv_bfloat16 hi = __float2bfloat16(o[u]);
        __nv_bfloat16 lo = __float2bfloat16(o[u] - __bfloat162float(hi));
        op[u] = hi; op[384 + u] = hi; op[768 + u] = lo;
    }
}

// ------------------------------- launcher -----------------------------------
extern "C" void kernel_launch(void* const* d_in, const int* in_sizes, int n_in,
                              void* d_out, int out_size)
{
    const float* values = (const float*)d_in[0];
    const float* coords = (const float*)d_in[1];
    const float* W_vqk  = (const float*)d_in[2];
    const float* b_vqk  = (const float*)d_in[3];
    const float* gm_vqk = (const float*)d_in[4];
    const float* W_vv   = (const float*)d_in[5];
    const float* b_vv   = (const float*)d_in[6];
    const float* W_cqk  = (const float*)d_in[7];
    const float* b_cqk  = (const float*)d_in[8];
    const float* gm_cqk = (const float*)d_in[9];
    const float* lam    = (const float*)d_in[10];
    const float* pos    = (const float*)d_in[11];
    const float* W_ov   = (const float*)d_in[12];
    const float* b_ov   = (const float*)d_in[13];
    float* out = (float*)d_out;

    __nv_bfloat16 *Av, *Ac, *Yb, *Bv, *Bc, *Bo;
    float *pv, *pc, *biasv;
    cudaGetSymbolAddress((void**)&Av, g_Av);
    cudaGetSymbolAddress((void**)&Ac, g_Ac);
    cudaGetSymbolAddress((void**)&Yb, g_Yb);
    cudaGetSymbolAddress((void**)&Bv, g_Bv);
    cudaGetSymbolAddress((void**)&Bc, g_Bc);
    cudaGetSymbolAddress((void**)&Bo, g_Bo);
    cudaGetSymbolAddress((void**)&pv, g_pv);
    cudaGetSymbolAddress((void**)&pc, g_pc);
    cudaGetSymbolAddress((void**)&biasv, g_biasv);

    // packing (bf16 compensated split)
    pack_A<<<(int)(((size_t)NTOK * 384 + 255) / 256), 256>>>(values, Av, 384);
    pack_A<<<(int)(((size_t)NTOK * 128 + 255) / 256), 256>>>(coords, Ac, 128);
    pack_Bv<<<(1152 * 384 + 255) / 256, 256>>>(W_vqk, W_vv, Bv);
    pack_B<<<(768 * 128 + 255) / 256, 256>>>(W_cqk, Bc, 128, 768);
    pack_B<<<(384 * 384 + 255) / 256, 256>>>(W_ov, Bo, 384, 384);
    bias_cat<<<5, 256>>>(b_vqk, b_vv);

    const int gsm = 65536;
    cudaFuncSetAttribute(gemm_mma, cudaFuncAttributeMaxDynamicSharedMemorySize, gsm);

    // projections (HMMA tensor path, K' = 3K)
    gemm_mma<<<dim3(1152 / 128, NTOK / 128), 256, gsm>>>(Av, Bv, biasv, pv, 1152, 1152);
    gemm_mma<<<dim3(768 / 128,  NTOK / 128), 256, gsm>>>(Ac, Bc, b_cqk, pc,  384,  768);

    // rmsnorm + interleaved split + roll + window layout
    scatter_k<<<NTOK, 256>>>(gm_vqk, gm_cqk, lam);

    // attention (writes bf16-split Y directly)
    const int asm_ = (64 * QSTR * 2 + 64 * 48 + 64 * 65 + 225) * (int)sizeof(float);
    cudaFuncSetAttribute(attn_k, cudaFuncAttributeMaxDynamicSharedMemorySize, asm_);
    attn_k<<<Bb * NH_ * NW_ * NW_, 256, asm_>>>(pos);

    // output projection
    gemm_mma<<<dim3(384 / 128, NTOK / 128), 256, gsm>>>(Yb, Bo, b_ov, out, 1152, 384);
}

// round 4
// speedup vs baseline: 1.9750x; 1.2667x over previous
#include <cuda_runtime.h>
#include <cuda_fp16.h>
#include <math.h>
#include <stdint.h>

#define Bb   2
#define Hh   192
#define Wd   192
#define NH_  8
#define HD_  48
#define NW_  24
#define NTOK (Bb*Hh*Wd)   // 73728

// ---------------- scratch (device globals; no runtime alloc) ----------------
__device__ __half g_Av[(size_t)NTOK * 768];    // values split [hi|lo]
__device__ __half g_Ac[(size_t)NTOK * 256];    // coords split
__device__ __half g_Yb[(size_t)NTOK * 768];    // attn out split
__device__ __half g_Bv[1152 * 768];            // W' combined vqk|vv [N, hi|hi]
__device__ __half g_Bc[768 * 256];             // W' cqk
__device__ __half g_Bo[384 * 768];             // W' ov
__device__ float g_biasv[1152];
__device__ float g_pv[(size_t)NTOK * 1152];    // raw vqk(768)|vv(384)
__device__ float g_pc[(size_t)NTOK * 768];     // raw cqk
__device__ float g_QF[(size_t)NTOK * NH_ * 96];
__device__ float g_KF[(size_t)NTOK * NH_ * 96];
__device__ float g_VB[(size_t)NTOK * NH_ * 48];

// ------------------------------ PTX helpers ---------------------------------
__device__ __forceinline__ uint32_t s2u(const void* p) {
    uint32_t a;
    asm("{ .reg .u64 t; cvta.to.shared.u64 t, %1; cvt.u32.u64 %0, t; }" : "=r"(a) : "l"(p));
    return a;
}
__device__ __forceinline__ void cp16(uint32_t dst, const void* src) {
    asm volatile("cp.async.cg.shared.global [%0], [%1], 16;" :: "r"(dst), "l"(src));
}
#define CP_COMMIT() asm volatile("cp.async.commit_group;" ::: "memory")
#define CP_WAIT1()  asm volatile("cp.async.wait_group 1;" ::: "memory")
#define CP_WAIT0()  asm volatile("cp.async.wait_group 0;" ::: "memory")

#define LDSM4(R0,R1,R2,R3,ADDR) \
    asm volatile("ldmatrix.sync.aligned.m8n8.x4.shared.b16 {%0,%1,%2,%3}, [%4];" \
                 : "=r"(R0), "=r"(R1), "=r"(R2), "=r"(R3) : "r"(ADDR))

#define MMA16816(D,A0,A1,A2,A3,B0,B1) \
    asm volatile("mma.sync.aligned.m16n8k16.row.col.f32.f16.f16.f32 " \
                 "{%0,%1,%2,%3},{%4,%5,%6,%7},{%8,%9},{%0,%1,%2,%3};" \
                 : "+f"(D[0]), "+f"(D[1]), "+f"(D[2]), "+f"(D[3]) \
                 : "r"(A0), "r"(A1), "r"(A2), "r"(A3), "r"(B0), "r"(B1))

// ------------------------ fused pack kernel (1 launch) -----------------------
// jobs: A_v (NTOK x 384), A_c (NTOK x 128), B_v (1152 x 384), B_c (768 x 128),
//       B_o (384 x 384)
#define T0 ((size_t)NTOK * 384)
#define T1 (T0 + (size_t)NTOK * 128)
#define T2 (T1 + 1152 * 384)
#define T3 (T2 + 768 * 128)
#define T4 (T3 + 384 * 384)
__global__ void pack_all(const float* __restrict__ values, const float* __restrict__ coords,
                         const float* __restrict__ Wqk, const float* __restrict__ Wvv,
                         const float* __restrict__ Wcqk, const float* __restrict__ Wov)
{
    size_t i = (size_t)blockIdx.x * 256 + threadIdx.x;
    if (i < T0) {                       // A_v split: exact activation
        size_t t = i / 384; int k = (int)(i - t * 384);
        float x = values[i];
        __half hi = __float2half_rn(x);
        __half lo = __float2half_rn(x - __half2float(hi));
        __half* row = g_Av + t * 768;
        row[k] = hi; row[384 + k] = lo;
    } else if (i < T1) {                // A_c split
        size_t j = i - T0;
        size_t t = j / 128; int k = (int)(j - t * 128);
        float x = coords[j];
        __half hi = __float2half_rn(x);
        __half lo = __float2half_rn(x - __half2float(hi));
        __half* row = g_Ac + t * 256;
        row[k] = hi; row[128 + k] = lo;
    } else if (i < T2) {                // B_v: quantized weight, duplicated
        int j = (int)(i - T1);
        int n = j / 384, k = j - (j / 384) * 384;
        float w = (n < 768) ? Wqk[(size_t)k * 768 + n] : Wvv[(size_t)k * 384 + (n - 768)];
        __half hi = __float2half_rn(w);
        __half* row = g_Bv + (size_t)n * 768;
        row[k] = hi; row[384 + k] = hi;
    } else if (i < T3) {                // B_c
        int j = (int)(i - T2);
        int n = j / 128, k = j - (j / 128) * 128;
        float w = Wcqk[(size_t)k * 768 + n];
        __half hi = __float2half_rn(w);
        __half* row = g_Bc + (size_t)n * 256;
        row[k] = hi; row[128 + k] = hi;
    } else if (i < T4) {                // B_o
        int j = (int)(i - T3);
        int n = j / 384, k = j - (j / 384) * 384;
        float w = Wov[(size_t)k * 384 + n];
        __half hi = __float2half_rn(w);
        __half* row = g_Bo + (size_t)n * 768;
        row[k] = hi; row[384 + k] = hi;
    }
}
__global__ void bias_cat(const float* __restrict__ a, const float* __restrict__ b) {
    int i = blockIdx.x * 256 + threadIdx.x;
    if (i < 1152) g_biasv[i] = (i < 768) ? a[i] : b[i - 768];
}

// --------- HMMA GEMM: C[M,N] = A'[M,K'] @ B'[N,K']^T + bias -----------------
// CTA tile 256x128, 8 warps (4 m x 2 n), warp tile 64x64.
// K chunked by 64 fp16 (128B SW128 rows), cp.async double-buffered.
// smem: A0 @0 (32K), A1 @32K, B0 @64K (16K), B1 @80K -> 96KB dynamic.
__global__ __launch_bounds__(256, 1) void gemm_mma(
    const __half* __restrict__ A, const __half* __restrict__ B,
    const float* __restrict__ bias, float* __restrict__ C, int Kp, int ldc)
{
    extern __shared__ __align__(1024) char smem[];
    const uint32_t sb = s2u(smem);
    const int tid = threadIdx.x, lane = tid & 31, wid = tid >> 5;
    const int m0 = blockIdx.y * 256, n0 = blockIdx.x * 128;
    const int wm = (wid & 3) << 6;       // warp m offset (64)
    const int wn = (wid >> 2) << 6;      // warp n offset (64)

    // ---- global->smem geometry: 32 rows x 8 cols16 per pass
    const int lrow = tid >> 3, lu = tid & 7;
    const size_t ldk = (size_t)Kp * 2;   // bytes per row
    const char* Asrc = (const char*)A + (size_t)(m0 + lrow) * ldk + lu * 16;
    const char* Bsrc = (const char*)B + (size_t)(n0 + lrow) * ldk + lu * 16;
    uint32_t dstA[8], dstB[4];
#pragma unroll
    for (int r = 0; r < 8; r++) {
        const int row = lrow + r * 32;
        dstA[r] = row * 128 + ((lu ^ (row & 7)) << 4);
    }
#pragma unroll
    for (int r = 0; r < 4; r++) dstB[r] = dstA[r];

    // ---- ldmatrix geometry
    const int q = lane >> 3, tr = lane & 7;
    const int qA = q >> 1, qB = q & 1;
    uint32_t rowoffA[4], xrA[4];
#pragma unroll
    for (int fm = 0; fm < 4; fm++) {
        const int row = wm + fm * 16 + tr + ((q & 1) << 3);
        rowoffA[fm] = row * 128; xrA[fm] = row & 7;
    }
    uint32_t rowoffB[4], xrB[4];
#pragma unroll
    for (int fn = 0; fn < 4; fn++) {
        const int row = wn + fn * 16 + tr + ((q >> 1) << 3);
        rowoffB[fn] = row * 128; xrB[fn] = row & 7;
    }

    float acc[4][8][4] = {};

    const int NC = Kp >> 6;
    // prefetch chunk 0
#pragma unroll
    for (int r = 0; r < 8; r++) cp16(sb + dstA[r], Asrc + (size_t)r * 32 * ldk);
#pragma unroll
    for (int r = 0; r < 4; r++) cp16(sb + 65536u + dstB[r], Bsrc + (size_t)r * 32 * ldk);
    CP_COMMIT();

    for (int c = 0; c < NC; c++) {
        const int buf = c & 1;
        if (c + 1 < NC) {
            const uint32_t ab = sb + (buf ^ 1) * 32768u;
            const uint32_t bb = sb + 65536u + (buf ^ 1) * 16384u;
            const char* An = Asrc + (size_t)(c + 1) * 128;
            const char* Bn = Bsrc + (size_t)(c + 1) * 128;
#pragma unroll
            for (int r = 0; r < 8; r++) cp16(ab + dstA[r], An + (size_t)r * 32 * ldk);
#pragma unroll
            for (int r = 0; r < 4; r++) cp16(bb + dstB[r], Bn + (size_t)r * 32 * ldk);
            CP_COMMIT();
            CP_WAIT1();
        } else {
            CP_WAIT0();
        }
        __syncthreads();

        const uint32_t Ab = sb + buf * 32768u;
        const uint32_t Bs = sb + 65536u + buf * 16384u;
#pragma unroll
        for (int ks = 0; ks < 4; ks++) {
            uint32_t a[4][4], bf[4][4];
#pragma unroll
            for (int fm = 0; fm < 4; fm++) {
                const uint32_t ad = Ab + rowoffA[fm] + ((((uint32_t)(ks * 2 + qA)) ^ xrA[fm]) << 4);
                LDSM4(a[fm][0], a[fm][1], a[fm][2], a[fm][3], ad);
            }
#pragma unroll
            for (int fn = 0; fn < 4; fn++) {
                const uint32_t bd = Bs + rowoffB[fn] + ((((uint32_t)(ks * 2 + qB)) ^ xrB[fn]) << 4);
                LDSM4(bf[fn][0], bf[fn][1], bf[fn][2], bf[fn][3], bd);
            }
#pragma unroll
            for (int fm = 0; fm < 4; fm++)
#pragma unroll
                for (int fn = 0; fn < 4; fn++) {
                    MMA16816(acc[fm][2 * fn],     a[fm][0], a[fm][1], a[fm][2], a[fm][3],
                             bf[fn][0], bf[fn][1]);
                    MMA16816(acc[fm][2 * fn + 1], a[fm][0], a[fm][1], a[fm][2], a[fm][3],
                             bf[fn][2], bf[fn][3]);
                }
        }
        __syncthreads();
    }

    // ---- epilogue
    const int er = lane >> 2, ec = (lane & 3) << 1;
#pragma unroll
    for (int fm = 0; fm < 4; fm++) {
#pragma unroll
        for (int fn = 0; fn < 8; fn++) {
            const int gm = m0 + wm + fm * 16 + er;
            const int gn = n0 + wn + fn * 8 + ec;
            const float2 bv = *(const float2*)(bias + gn);
            float2 o0, o1;
            o0.x = acc[fm][fn][0] + bv.x; o0.y = acc[fm][fn][1] + bv.y;
            o1.x = acc[fm][fn][2] + bv.x; o1.y = acc[fm][fn][3] + bv.y;
            *(float2*)(C + (size_t)gm * ldc + gn) = o0;
            *(float2*)(C + (size_t)(gm + 8) * ldc + gn) = o1;
        }
    }
}

// ------------- RMSNorm + interleaved split + roll + window scatter ----------
__global__ __launch_bounds__(256) void scatter_k(
    const float* __restrict__ gvqk, const float* __restrict__ gcqk,
    const float* __restrict__ lamp)
{
    __shared__ float sv[1152];
    __shared__ float sc[768];
    __shared__ float red[16];
    const int p = blockIdx.x, tid = threadIdx.x;
    const float* pv = g_pv + (size_t)p * 1152;
    const float* pc = g_pc + (size_t)p * 768;
    for (int i = tid; i < 1152; i += 256) sv[i] = pv[i];
    for (int i = tid; i < 768;  i += 256) sc[i] = pc[i];
    __syncthreads();

    float s1 = 0.f, s2 = 0.f;
    for (int i = tid; i < 768; i += 256) {
        float a = sv[i]; s1 += a * a;
        float c = sc[i]; s2 += c * c;
    }
#pragma unroll
    for (int o = 16; o; o >>= 1) {
        s1 += __shfl_xor_sync(0xffffffffu, s1, o);
        s2 += __shfl_xor_sync(0xffffffffu, s2, o);
    }
    if ((tid & 31) == 0) { red[tid >> 5] = s1; red[8 + (tid >> 5)] = s2; }
    __syncthreads();
    float S1 = 0.f, S2 = 0.f;
#pragma unroll
    for (int i = 0; i < 8; i++) { S1 += red[i]; S2 += red[8 + i]; }
    const float r1 = rsqrtf(S1 * (1.f / 768.f) + 1e-6f);
    const float r2 = rsqrtf(S2 * (1.f / 768.f) + 1e-6f);
    const float lam = lamp[0];

    const int b = p / (Hh * Wd);
    const int rem = p - b * (Hh * Wd);
    const int y = rem / Wd, x = rem - (rem / Wd) * Wd;
    const int yr = (y + Hh - 4) % Hh, xr = (x + Wd - 4) % Wd;
    const int wy = yr >> 3, wx = xr >> 3;
    const int tok = ((yr & 7) << 3) | (xr & 7);

    const int head = tid >> 5, lane = tid & 31;
    const size_t wbase = ((((size_t)b * NH_ + head) * NW_ + wy) * NW_ + wx) * 64 + tok;
    float* QFp = g_QF + wbase * 96;
    float* KFp = g_KF + wbase * 96;
    float* VBp = g_VB + wbase * 48;

#pragma unroll
    for (int jj = 0; jj < 3; jj++) {
        const int j = lane + jj * 32;
        float qv_, kv_;
        if (j < 48) {
            const int d = j * 8 + head;
            qv_ = sv[3 * d]; kv_ = sv[3 * d + 1];
            if (d < 256) { qv_ *= r1 * gvqk[3 * d]; kv_ *= r1 * gvqk[3 * d + 1]; }
        } else {
            const int d = (j - 48) * 8 + head;
            qv_ = sc[2 * d]     * r2 * gcqk[2 * d] * lam;
            kv_ = sc[2 * d + 1] * r2 * gcqk[2 * d + 1];
        }
        QFp[j] = qv_; KFp[j] = kv_;
    }
    {
        const int d = lane * 8 + head;
        float v = sv[3 * d + 2];
        if (d < 256) v *= r1 * gvqk[3 * d + 2];
        VBp[lane] = v;
        if (lane < 16) {
            const int d2 = (lane + 32) * 8 + head;
            VBp[lane + 32] = sv[3 * d2 + 2];   // d2 >= 256 always: raw
        }
    }
}

// ---------------------------- windowed attention ----------------------------
#define QSTR 97

__global__ __launch_bounds__(256) void attn_k(const float* __restrict__ pos_emb)
{
    extern __shared__ float sm[];
    float* Qs = sm;
    float* Ks = sm + 64 * QSTR;
    float* Vs = Ks + 64 * QSTR;
    float* Ds = Vs + 64 * 48;
    float* Ps = Ds + 64 * 65;

    int blk = blockIdx.x;
    const int wx = blk % NW_; blk /= NW_;
    const int wy = blk % NW_; blk /= NW_;
    const int head = blk % NH_;
    const int b = blk / NH_;
    const int tid = threadIdx.x;

    const size_t wbase = ((((size_t)b * NH_ + head) * NW_ + wy) * NW_ + wx) * 64;
    const float* qg = g_QF + wbase * 96;
    const float* kg = g_KF + wbase * 96;
    const float* vg = g_VB + wbase * 48;

    for (int i = tid; i < 64 * 96; i += 256) {
        const int t0 = i / 96, e = i - t0 * 96;
        Qs[t0 * QSTR + e] = qg[i];
        Ks[t0 * QSTR + e] = kg[i];
    }
    for (int i = tid; i < 64 * 48 / 4; i += 256)
        *(float4*)&Vs[i * 4] = ((const float4*)vg)[i];
    for (int i = tid; i < 225; i += 256) Ps[i] = pos_emb[i];
    __syncthreads();

    const int ty = tid >> 4, tx = tid & 15;
    float acc[4][4] = {};
#pragma unroll 4
    for (int e = 0; e < 96; e++) {
        float q0 = Qs[(ty * 4 + 0) * QSTR + e];
        float q1 = Qs[(ty * 4 + 1) * QSTR + e];
        float q2 = Qs[(ty * 4 + 2) * QSTR + e];
        float q3 = Qs[(ty * 4 + 3) * QSTR + e];
        float k0 = Ks[(tx * 4 + 0) * QSTR + e];
        float k1 = Ks[(tx * 4 + 1) * QSTR + e];
        float k2 = Ks[(tx * 4 + 2) * QSTR + e];
        float k3 = Ks[(tx * 4 + 3) * QSTR + e];
        acc[0][0] += q0 * k0; acc[0][1] += q0 * k1; acc[0][2] += q0 * k2; acc[0][3] += q0 * k3;
        acc[1][0] += q1 * k0; acc[1][1] += q1 * k1; acc[1][2] += q1 * k2; acc[1][3] += q1 * k3;
        acc[2][0] += q2 * k0; acc[2][1] += q2 * k1; acc[2][2] += q2 * k2; acc[2][3] += q2 * k3;
        acc[3][0] += q3 * k0; acc[3][1] += q3 * k1; acc[3][2] += q3 * k2; acc[3][3] += q3 * k3;
    }
    const float scale = 0.14433756729740643f;   // 1/sqrt(48)
    const bool lastR = (wy == NW_ - 1), lastC = (wx == NW_ - 1);
#pragma unroll
    for (int i4 = 0; i4 < 4; i4++) {
        const int i = ty * 4 + i4;
#pragma unroll
        for (int j4 = 0; j4 < 4; j4++) {
            const int j = tx * 4 + j4;
            float v = acc[i4][j4] * scale
                    + Ps[((j >> 3) - (i >> 3) + 7) * 15 + ((j & 7) - (i & 7) + 7)];
            if (lastR && (((i >= 32) ? 1 : 0) ^ ((j >= 32) ? 1 : 0)))           v = -INFINITY;
            if (lastC && ((((i & 7) >= 4) ? 1 : 0) ^ (((j & 7) >= 4) ? 1 : 0))) v = -INFINITY;
            Ds[i * 65 + j] = v;
        }
    }
    __syncthreads();

    const int r = tid >> 2, qd = tid & 3;
    float m = -INFINITY;
#pragma unroll
    for (int j = 0; j < 16; j++) m = fmaxf(m, Ds[r * 65 + qd * 16 + j]);
    m = fmaxf(m, __shfl_xor_sync(0xffffffffu, m, 1));
    m = fmaxf(m, __shfl_xor_sync(0xffffffffu, m, 2));
    float s = 0.f;
#pragma unroll
    for (int j = 0; j < 16; j++) {
        float eV = __expf(Ds[r * 65 + qd * 16 + j] - m);
        Ds[r * 65 + qd * 16 + j] = eV;
        s += eV;
    }
    s += __shfl_xor_sync(0xffffffffu, s, 1);
    s += __shfl_xor_sync(0xffffffffu, s, 2);
    const float inv = 1.f / s;
    __syncthreads();

    float o[12] = {};
    for (int j = 0; j < 64; j++) {
        const float a = Ds[r * 65 + j] * inv;
        const float* vp = &Vs[j * 48 + qd * 12];
#pragma unroll
        for (int u = 0; u < 3; u++) {
            float4 v4 = *(const float4*)&vp[u * 4];
            o[u * 4 + 0] += a * v4.x; o[u * 4 + 1] += a * v4.y;
            o[u * 4 + 2] += a * v4.z; o[u * 4 + 3] += a * v4.w;
        }
    }
    const int Y = wy * 8 + (r >> 3), X = wx * 8 + (r & 7);
    const size_t t = ((size_t)b * Hh + Y) * Wd + X;
    __half* op = g_Yb + t * 768 + head * HD_ + qd * 12;
#pragma unroll
    for (int u = 0; u < 12; u++) {
        __half hi = __float2half_rn(o[u]);
        __half lo = __float2half_rn(o[u] - __half2float(hi));
        op[u] = hi; op[384 + u] = lo;
    }
}

// ------------------------------- launcher -----------------------------------
extern "C" void kernel_launch(void* const* d_in, const int* in_sizes, int n_in,
                              void* d_out, int out_size)
{
    const float* values = (const float*)d_in[0];
    const float* coords = (const float*)d_in[1];
    const float* W_vqk  = (const float*)d_in[2];
    const float* b_vqk  = (const float*)d_in[3];
    const float* gm_vqk = (const float*)d_in[4];
    const float* W_vv   = (const float*)d_in[5];
    const float* b_vv   = (const float*)d_in[6];
    const float* W_cqk  = (const float*)d_in[7];
    const float* b_cqk  = (const float*)d_in[8];
    const float* gm_cqk = (const float*)d_in[9];
    const float* lam    = (const float*)d_in[10];
    const float* pos    = (const float*)d_in[11];
    const float* W_ov   = (const float*)d_in[12];
    const float* b_ov   = (const float*)d_in[13];
    float* out = (float*)d_out;

    __half *Av, *Ac, *Yb, *Bv, *Bc, *Bo;
    float *pv, *pc, *biasv;
    cudaGetSymbolAddress((void**)&Av, g_Av);
    cudaGetSymbolAddress((void**)&Ac, g_Ac);
    cudaGetSymbolAddress((void**)&Yb, g_Yb);
    cudaGetSymbolAddress((void**)&Bv, g_Bv);
    cudaGetSymbolAddress((void**)&Bc, g_Bc);
    cudaGetSymbolAddress((void**)&Bo, g_Bo);
    cudaGetSymbolAddress((void**)&pv, g_pv);
    cudaGetSymbolAddress((void**)&pc, g_pc);
    cudaGetSymbolAddress((void**)&biasv, g_biasv);

    // 1) fused packing (fp16 2-term split)
    pack_all<<<(int)((T4 + 255) / 256), 256>>>(values, coords, W_vqk, W_vv, W_cqk, W_ov);
    // 2) bias concat (tiny)
    bias_cat<<<5, 256>>>(b_vqk, b_vv);

    const int gsm = 98304;
    cudaFuncSetAttribute(gemm_mma, cudaFuncAttributeMaxDynamicSharedMemorySize, gsm);

    // 3) coords projection, 4) values projection (profiled slot)
    gemm_mma<<<dim3(768 / 128,  NTOK / 256), 256, gsm>>>(Ac, Bc, b_cqk, pc,  256,  768);
    gemm_mma<<<dim3(1152 / 128, NTOK / 256), 256, gsm>>>(Av, Bv, biasv, pv,  768, 1152);

    // 5) rmsnorm + interleaved split + roll + window layout
    scatter_k<<<NTOK, 256>>>(gm_vqk, gm_cqk, lam);

    // 6) attention (writes fp16-split Y directly)
    const int asm_ = (64 * QSTR * 2 + 64 * 48 + 64 * 65 + 225) * (int)sizeof(float);
    cudaFuncSetAttribute(attn_k, cudaFuncAttributeMaxDynamicSharedMemorySize, asm_);
    attn_k<<<Bb * NH_ * NW_ * NW_, 256, asm_>>>(pos);

    // 7) output projection
    gemm_mma<<<dim3(384 / 128, NTOK / 256), 256, gsm>>>(Yb, Bo, b_ov, out, 768, 384);
}

// round 5
// speedup vs baseline: 2.1522x; 1.0897x over previous
#include <cuda_runtime.h>
#include <cuda_fp16.h>
#include <math.h>
#include <stdint.h>

#define Bb   2
#define Hh   192
#define Wd   192
#define NH_  8
#define HD_  48
#define NW_  24
#define NTOK (Bb*Hh*Wd)   // 73728

// ---------------- scratch (device globals; no runtime alloc) ----------------
__device__ __half g_Av[(size_t)NTOK * 768];    // values split [hi|lo]
__device__ __half g_Ac[(size_t)NTOK * 256];    // coords split
__device__ __half g_Yb[(size_t)NTOK * 768];    // attn out split
__device__ __half g_Bv[1152 * 768];            // W' combined vqk|vv [N, hi|hi]
__device__ __half g_Bc[768 * 256];             // W' cqk
__device__ __half g_Bo[384 * 768];             // W' ov
__device__ float g_biasv[1152];
__device__ float g_pv[(size_t)NTOK * 1152];    // raw vqk(768)|vv(384)
__device__ float g_pc[(size_t)NTOK * 768];     // raw cqk
__device__ __half g_QF2[(size_t)NTOK * NH_ * 192];  // [hi(96)|lo(96)] per token/head
__device__ __half g_KF2[(size_t)NTOK * NH_ * 192];
__device__ float g_VB[(size_t)NTOK * NH_ * 48];

// ------------------------------ PTX helpers ---------------------------------
__device__ __forceinline__ uint32_t s2u(const void* p) {
    uint32_t a;
    asm("{ .reg .u64 t; cvta.to.shared.u64 t, %1; cvt.u32.u64 %0, t; }" : "=r"(a) : "l"(p));
    return a;
}
__device__ __forceinline__ void cp16(uint32_t dst, const void* src) {
    asm volatile("cp.async.cg.shared.global [%0], [%1], 16;" :: "r"(dst), "l"(src));
}
#define CP_COMMIT() asm volatile("cp.async.commit_group;" ::: "memory")
#define CP_WAIT1()  asm volatile("cp.async.wait_group 1;" ::: "memory")
#define CP_WAIT0()  asm volatile("cp.async.wait_group 0;" ::: "memory")

#define LDSM4(R0,R1,R2,R3,ADDR) \
    asm volatile("ldmatrix.sync.aligned.m8n8.x4.shared.b16 {%0,%1,%2,%3}, [%4];" \
                 : "=r"(R0), "=r"(R1), "=r"(R2), "=r"(R3) : "r"(ADDR))

#define MMA16816(D,A0,A1,A2,A3,B0,B1) \
    asm volatile("mma.sync.aligned.m16n8k16.row.col.f32.f16.f16.f32 " \
                 "{%0,%1,%2,%3},{%4,%5,%6,%7},{%8,%9},{%0,%1,%2,%3};" \
                 : "+f"(D[0]), "+f"(D[1]), "+f"(D[2]), "+f"(D[3]) \
                 : "r"(A0), "r"(A1), "r"(A2), "r"(A3), "r"(B0), "r"(B1))

// ------------------------ fused pack kernel (1 launch) -----------------------
#define T0 ((size_t)NTOK * 384)
#define T1 (T0 + (size_t)NTOK * 128)
#define T2 (T1 + 1152 * 384)
#define T3 (T2 + 768 * 128)
#define T4 (T3 + 384 * 384)
__global__ void pack_all(const float* __restrict__ values, const float* __restrict__ coords,
                         const float* __restrict__ Wqk, const float* __restrict__ Wvv,
                         const float* __restrict__ Wcqk, const float* __restrict__ Wov)
{
    size_t i = (size_t)blockIdx.x * 256 + threadIdx.x;
    if (i < T0) {                       // A_v split: exact activation
        size_t t = i / 384; int k = (int)(i - t * 384);
        float x = values[i];
        __half hi = __float2half_rn(x);
        __half lo = __float2half_rn(x - __half2float(hi));
        __half* row = g_Av + t * 768;
        row[k] = hi; row[384 + k] = lo;
    } else if (i < T1) {                // A_c split
        size_t j = i - T0;
        size_t t = j / 128; int k = (int)(j - t * 128);
        float x = coords[j];
        __half hi = __float2half_rn(x);
        __half lo = __float2half_rn(x - __half2float(hi));
        __half* row = g_Ac + t * 256;
        row[k] = hi; row[128 + k] = lo;
    } else if (i < T2) {                // B_v: quantized weight, duplicated
        int j = (int)(i - T1);
        int n = j / 384, k = j - (j / 384) * 384;
        float w = (n < 768) ? Wqk[(size_t)k * 768 + n] : Wvv[(size_t)k * 384 + (n - 768)];
        __half hi = __float2half_rn(w);
        __half* row = g_Bv + (size_t)n * 768;
        row[k] = hi; row[384 + k] = hi;
    } else if (i < T3) {                // B_c
        int j = (int)(i - T2);
        int n = j / 128, k = j - (j / 128) * 128;
        float w = Wcqk[(size_t)k * 768 + n];
        __half hi = __float2half_rn(w);
        __half* row = g_Bc + (size_t)n * 256;
        row[k] = hi; row[128 + k] = hi;
    } else if (i < T4) {                // B_o
        int j = (int)(i - T3);
        int n = j / 384, k = j - (j / 384) * 384;
        float w = Wov[(size_t)k * 384 + n];
        __half hi = __float2half_rn(w);
        __half* row = g_Bo + (size_t)n * 768;
        row[k] = hi; row[384 + k] = hi;
    }
}
__global__ void bias_cat(const float* __restrict__ a, const float* __restrict__ b) {
    int i = blockIdx.x * 256 + threadIdx.x;
    if (i < 1152) g_biasv[i] = (i < 768) ? a[i] : b[i - 768];
}

// --------- HMMA GEMM: C[M,N] = A'[M,K'] @ B'[N,K']^T + bias -----------------
// CTA tile 128x128, 8 warps (4 m x 2 n), warp tile 32x64, 2 CTAs/SM.
// K chunked by 64 fp16 (128B SW128 rows), cp.async double-buffered. 64KB smem.
__global__ __launch_bounds__(256, 2) void gemm_mma(
    const __half* __restrict__ A, const __half* __restrict__ B,
    const float* __restrict__ bias, float* __restrict__ C, int Kp, int ldc)
{
    extern __shared__ __align__(1024) char smem[];
    const uint32_t sb = s2u(smem);
    const int tid = threadIdx.x, lane = tid & 31, wid = tid >> 5;
    const int m0 = blockIdx.y * 128, n0 = blockIdx.x * 128;
    const int wm = (wid & 3) << 5;       // warp m offset (32)
    const int wn = (wid >> 2) << 6;      // warp n offset (64)

    const int lrow = tid >> 3, lu = tid & 7;
    const size_t ldk = (size_t)Kp * 2;
    const char* Asrc = (const char*)A + (size_t)(m0 + lrow) * ldk + lu * 16;
    const char* Bsrc = (const char*)B + (size_t)(n0 + lrow) * ldk + lu * 16;
    uint32_t dsto[4];
#pragma unroll
    for (int r = 0; r < 4; r++) {
        const int row = lrow + r * 32;
        dsto[r] = row * 128 + ((lu ^ (row & 7)) << 4);
    }

    const int q = lane >> 3, tr = lane & 7;
    const int qA = q >> 1, qB = q & 1;
    uint32_t rowoffA[2], xrA[2];
#pragma unroll
    for (int fm = 0; fm < 2; fm++) {
        const int row = wm + fm * 16 + tr + ((q & 1) << 3);
        rowoffA[fm] = row * 128; xrA[fm] = row & 7;
    }
    uint32_t rowoffB[4], xrB[4];
#pragma unroll
    for (int fn = 0; fn < 4; fn++) {
        const int row = wn + fn * 16 + tr + ((q >> 1) << 3);
        rowoffB[fn] = row * 128; xrB[fn] = row & 7;
    }

    float acc[2][8][4] = {};

    const int NC = Kp >> 6;
#pragma unroll
    for (int r = 0; r < 4; r++) {
        cp16(sb + dsto[r],          Asrc + (size_t)r * 32 * ldk);
        cp16(sb + 32768u + dsto[r], Bsrc + (size_t)r * 32 * ldk);
    }
    CP_COMMIT();

    for (int c = 0; c < NC; c++) {
        const int buf = c & 1;
        if (c + 1 < NC) {
            const uint32_t ab = sb + (buf ^ 1) * 16384u;
            const uint32_t bb = sb + 32768u + (buf ^ 1) * 16384u;
            const char* An = Asrc + (size_t)(c + 1) * 128;
            const char* Bn = Bsrc + (size_t)(c + 1) * 128;
#pragma unroll
            for (int r = 0; r < 4; r++) {
                cp16(ab + dsto[r], An + (size_t)r * 32 * ldk);
                cp16(bb + dsto[r], Bn + (size_t)r * 32 * ldk);
            }
            CP_COMMIT();
            CP_WAIT1();
        } else {
            CP_WAIT0();
        }
        __syncthreads();

        const uint32_t Ab = sb + buf * 16384u;
        const uint32_t Bs = sb + 32768u + buf * 16384u;
#pragma unroll
        for (int ks = 0; ks < 4; ks++) {
            uint32_t a[2][4], bf[4][4];
#pragma unroll
            for (int fm = 0; fm < 2; fm++) {
                const uint32_t ad = Ab + rowoffA[fm] + ((((uint32_t)(ks * 2 + qA)) ^ xrA[fm]) << 4);
                LDSM4(a[fm][0], a[fm][1], a[fm][2], a[fm][3], ad);
            }
#pragma unroll
            for (int fn = 0; fn < 4; fn++) {
                const uint32_t bd = Bs + rowoffB[fn] + ((((uint32_t)(ks * 2 + qB)) ^ xrB[fn]) << 4);
                LDSM4(bf[fn][0], bf[fn][1], bf[fn][2], bf[fn][3], bd);
            }
#pragma unroll
            for (int fm = 0; fm < 2; fm++)
#pragma unroll
                for (int fn = 0; fn < 4; fn++) {
                    MMA16816(acc[fm][2 * fn],     a[fm][0], a[fm][1], a[fm][2], a[fm][3],
                             bf[fn][0], bf[fn][1]);
                    MMA16816(acc[fm][2 * fn + 1], a[fm][0], a[fm][1], a[fm][2], a[fm][3],
                             bf[fn][2], bf[fn][3]);
                }
        }
        __syncthreads();
    }

    const int er = lane >> 2, ec = (lane & 3) << 1;
#pragma unroll
    for (int fm = 0; fm < 2; fm++) {
#pragma unroll
        for (int fn = 0; fn < 8; fn++) {
            const int gm = m0 + wm + fm * 16 + er;
            const int gn = n0 + wn + fn * 8 + ec;
            const float2 bv = *(const float2*)(bias + gn);
            float2 o0, o1;
            o0.x = acc[fm][fn][0] + bv.x; o0.y = acc[fm][fn][1] + bv.y;
            o1.x = acc[fm][fn][2] + bv.x; o1.y = acc[fm][fn][3] + bv.y;
            *(float2*)(C + (size_t)gm * ldc + gn) = o0;
            *(float2*)(C + (size_t)(gm + 8) * ldc + gn) = o1;
        }
    }
}

// ------------- RMSNorm + interleaved split + roll + window scatter ----------
__global__ __launch_bounds__(256) void scatter_k(
    const float* __restrict__ gvqk, const float* __restrict__ gcqk,
    const float* __restrict__ lamp)
{
    __shared__ float sv[1152];
    __shared__ float sc[768];
    __shared__ float red[16];
    const int p = blockIdx.x, tid = threadIdx.x;
    const float* pv = g_pv + (size_t)p * 1152;
    const float* pc = g_pc + (size_t)p * 768;
    for (int i = tid; i < 1152; i += 256) sv[i] = pv[i];
    for (int i = tid; i < 768;  i += 256) sc[i] = pc[i];
    __syncthreads();

    float s1 = 0.f, s2 = 0.f;
    for (int i = tid; i < 768; i += 256) {
        float a = sv[i]; s1 += a * a;
        float c = sc[i]; s2 += c * c;
    }
#pragma unroll
    for (int o = 16; o; o >>= 1) {
        s1 += __shfl_xor_sync(0xffffffffu, s1, o);
        s2 += __shfl_xor_sync(0xffffffffu, s2, o);
    }
    if ((tid & 31) == 0) { red[tid >> 5] = s1; red[8 + (tid >> 5)] = s2; }
    __syncthreads();
    float S1 = 0.f, S2 = 0.f;
#pragma unroll
    for (int i = 0; i < 8; i++) { S1 += red[i]; S2 += red[8 + i]; }
    const float r1 = rsqrtf(S1 * (1.f / 768.f) + 1e-6f);
    const float r2 = rsqrtf(S2 * (1.f / 768.f) + 1e-6f);
    const float lam = lamp[0];

    const int b = p / (Hh * Wd);
    const int rem = p - b * (Hh * Wd);
    const int y = rem / Wd, x = rem - (rem / Wd) * Wd;
    const int yr = (y + Hh - 4) % Hh, xr = (x + Wd - 4) % Wd;
    const int wy = yr >> 3, wx = xr >> 3;
    const int tok = ((yr & 7) << 3) | (xr & 7);

    const int head = tid >> 5, lane = tid & 31;
    const size_t wbase = ((((size_t)b * NH_ + head) * NW_ + wy) * NW_ + wx) * 64 + tok;
    __half* Q2p = g_QF2 + wbase * 192;
    __half* K2p = g_KF2 + wbase * 192;
    float* VBp = g_VB + wbase * 48;

#pragma unroll
    for (int jj = 0; jj < 3; jj++) {
        const int j = lane + jj * 32;
        float qv_, kv_;
        if (j < 48) {
            const int d = j * 8 + head;
            qv_ = sv[3 * d]; kv_ = sv[3 * d + 1];
            if (d < 256) { qv_ *= r1 * gvqk[3 * d]; kv_ *= r1 * gvqk[3 * d + 1]; }
        } else {
            const int d = (j - 48) * 8 + head;
            qv_ = sc[2 * d]     * r2 * gcqk[2 * d] * lam;
            kv_ = sc[2 * d + 1] * r2 * gcqk[2 * d + 1];
        }
        __half qh = __float2half_rn(qv_);
        __half kh = __float2half_rn(kv_);
        Q2p[j] = qh; Q2p[96 + j] = __float2half_rn(qv_ - __half2float(qh));
        K2p[j] = kh; K2p[96 + j] = __float2half_rn(kv_ - __half2float(kh));
    }
    {
        const int d = lane * 8 + head;
        float v = sv[3 * d + 2];
        if (d < 256) v *= r1 * gvqk[3 * d + 2];
        VBp[lane] = v;
        if (lane < 16) {
            const int d2 = (lane + 32) * 8 + head;
            VBp[lane + 32] = sv[3 * d2 + 2];   // d2 >= 256 always: raw
        }
    }
}

// ---------------------------- windowed attention ----------------------------
// smem: Q2 64x200 half @0 (25600B) | K2 @25600 | Vs 64x48 f32 @51200 (12288B)
//       Ds 64x65 f32 @63488 (16640B) | Ps 225 f32 @80128 (900B)  total 81028B
__global__ __launch_bounds__(256) void attn_k(const float* __restrict__ pos_emb)
{
    extern __shared__ __align__(128) char smx[];
    __half* Q2 = (__half*)smx;
    __half* K2 = (__half*)(smx + 25600);
    float* Vs  = (float*)(smx + 51200);
    float* Ds  = (float*)(smx + 63488);
    float* Ps  = (float*)(smx + 80128);

    int blk = blockIdx.x;
    const int wx = blk % NW_; blk /= NW_;
    const int wy = blk % NW_; blk /= NW_;
    const int head = blk % NH_;
    const int b = blk / NH_;
    const int tid = threadIdx.x;

    const size_t wbase = ((((size_t)b * NH_ + head) * NW_ + wy) * NW_ + wx) * 64;
    const char* qg = (const char*)(g_QF2 + wbase * 192);
    const char* kg = (const char*)(g_KF2 + wbase * 192);
    const float* vg = g_VB + wbase * 48;

    for (int i = tid; i < 64 * 24; i += 256) {
        const int t = i / 24, u = i - t * 24;
        *(uint4*)((char*)Q2 + t * 400 + u * 16) = *(const uint4*)(qg + t * 384 + u * 16);
        *(uint4*)((char*)K2 + t * 400 + u * 16) = *(const uint4*)(kg + t * 384 + u * 16);
    }
    for (int i = tid; i < 64 * 48 / 4; i += 256)
        *(float4*)&Vs[i * 4] = ((const float4*)vg)[i];
    for (int i = tid; i < 225; i += 256) Ps[i] = pos_emb[i];
    __syncthreads();

    // ---- QK^T via HMMA, exact 3-pass fp16 split (hi.hi + lo.hi + hi.lo) ----
    const int lane = tid & 31, w = tid >> 5;
    const int wq = w & 3, wk = w >> 2;
    const int q = lane >> 3, tr = lane & 7;
    const uint32_t sQ = s2u(Q2), sK = s2u(K2);
    const uint32_t aBase = sQ + (uint32_t)(16 * wq + tr + ((q & 1) << 3)) * 400 + ((q >> 1) << 4);
    uint32_t bBase[2];
    bBase[0] = sK + (uint32_t)(32 * wk + tr + ((q >> 1) << 3)) * 400 + ((q & 1) << 4);
    bBase[1] = bBase[0] + 16 * 400;

    float acc[4][4] = {};
#pragma unroll
    for (int s = 0; s < 18; s++) {
        const int ca = (s < 12) ? s : s - 12;   // Q chunk: hi(0-5) lo(6-11) hi(0-5)
        const int cb = (s < 6) ? s : s - 6;     // K chunk: hi(0-5) hi(0-5) lo(6-11)
        uint32_t a0, a1, a2, a3;
        LDSM4(a0, a1, a2, a3, aBase + ca * 32);
#pragma unroll
        for (int fn = 0; fn < 2; fn++) {
            uint32_t b0, b1, b2, b3;
            LDSM4(b0, b1, b2, b3, bBase[fn] + cb * 32);
            MMA16816(acc[2 * fn],     a0, a1, a2, a3, b0, b1);
            MMA16816(acc[2 * fn + 1], a0, a1, a2, a3, b2, b3);
        }
    }

    const float scale = 0.14433756729740643f;   // 1/sqrt(48)
    const bool lastR = (wy == NW_ - 1), lastC = (wx == NW_ - 1);
#pragma unroll
    for (int f = 0; f < 4; f++) {
#pragma unroll
        for (int r = 0; r < 4; r++) {
            const int i = 16 * wq + (lane >> 2) + ((r >> 1) << 3);
            const int j = 32 * wk + 8 * f + ((lane & 3) << 1) + (r & 1);
            float v = acc[f][r] * scale
                    + Ps[((j >> 3) - (i >> 3) + 7) * 15 + ((j & 7) - (i & 7) + 7)];
            if (lastR && (((i >= 32) ? 1 : 0) ^ ((j >= 32) ? 1 : 0)))           v = -INFINITY;
            if (lastC && ((((i & 7) >= 4) ? 1 : 0) ^ (((j & 7) >= 4) ? 1 : 0))) v = -INFINITY;
            Ds[i * 65 + j] = v;
        }
    }
    __syncthreads();

    // ---- softmax (unchanged) ----
    const int r = tid >> 2, qd = tid & 3;
    float m = -INFINITY;
#pragma unroll
    for (int j = 0; j < 16; j++) m = fmaxf(m, Ds[r * 65 + qd * 16 + j]);
    m = fmaxf(m, __shfl_xor_sync(0xffffffffu, m, 1));
    m = fmaxf(m, __shfl_xor_sync(0xffffffffu, m, 2));
    float s = 0.f;
#pragma unroll
    for (int j = 0; j < 16; j++) {
        float eV = __expf(Ds[r * 65 + qd * 16 + j] - m);
        Ds[r * 65 + qd * 16 + j] = eV;
        s += eV;
    }
    s += __shfl_xor_sync(0xffffffffu, s, 1);
    s += __shfl_xor_sync(0xffffffffu, s, 2);
    const float inv = 1.f / s;
    __syncthreads();

    // ---- AV (fp32 FFMA, unchanged) ----
    float o[12] = {};
    for (int j = 0; j < 64; j++) {
        const float a = Ds[r * 65 + j] * inv;
        const float* vp = &Vs[j * 48 + qd * 12];
#pragma unroll
        for (int u = 0; u < 3; u++) {
            float4 v4 = *(const float4*)&vp[u * 4];
            o[u * 4 + 0] += a * v4.x; o[u * 4 + 1] += a * v4.y;
            o[u * 4 + 2] += a * v4.z; o[u * 4 + 3] += a * v4.w;
        }
    }
    const int Y = wy * 8 + (r >> 3), X = wx * 8 + (r & 7);
    const size_t t = ((size_t)b * Hh + Y) * Wd + X;
    __half* op = g_Yb + t * 768 + head * HD_ + qd * 12;
#pragma unroll
    for (int u = 0; u < 12; u++) {
        __half hi = __float2half_rn(o[u]);
        __half lo = __float2half_rn(o[u] - __half2float(hi));
        op[u] = hi; op[384 + u] = lo;
    }
}

// ------------------------------- launcher -----------------------------------
extern "C" void kernel_launch(void* const* d_in, const int* in_sizes, int n_in,
                              void* d_out, int out_size)
{
    const float* values = (const float*)d_in[0];
    const float* coords = (const float*)d_in[1];
    const float* W_vqk  = (const float*)d_in[2];
    const float* b_vqk  = (const float*)d_in[3];
    const float* gm_vqk = (const float*)d_in[4];
    const float* W_vv   = (const float*)d_in[5];
    const float* b_vv   = (const float*)d_in[6];
    const float* W_cqk  = (const float*)d_in[7];
    const float* b_cqk  = (const float*)d_in[8];
    const float* gm_cqk = (const float*)d_in[9];
    const float* lam    = (const float*)d_in[10];
    const float* pos    = (const float*)d_in[11];
    const float* W_ov   = (const float*)d_in[12];
    const float* b_ov   = (const float*)d_in[13];
    float* out = (float*)d_out;

    __half *Av, *Ac, *Yb, *Bv, *Bc, *Bo;
    float *pv, *pc, *biasv;
    cudaGetSymbolAddress((void**)&Av, g_Av);
    cudaGetSymbolAddress((void**)&Ac, g_Ac);
    cudaGetSymbolAddress((void**)&Yb, g_Yb);
    cudaGetSymbolAddress((void**)&Bv, g_Bv);
    cudaGetSymbolAddress((void**)&Bc, g_Bc);
    cudaGetSymbolAddress((void**)&Bo, g_Bo);
    cudaGetSymbolAddress((void**)&pv, g_pv);
    cudaGetSymbolAddress((void**)&pc, g_pc);
    cudaGetSymbolAddress((void**)&biasv, g_biasv);

    pack_all<<<(int)((T4 + 255) / 256), 256>>>(values, coords, W_vqk, W_vv, W_cqk, W_ov);
    bias_cat<<<5, 256>>>(b_vqk, b_vv);

    const int gsm = 65536;
    cudaFuncSetAttribute(gemm_mma, cudaFuncAttributeMaxDynamicSharedMemorySize, gsm);

    gemm_mma<<<dim3(768 / 128,  NTOK / 128), 256, gsm>>>(Ac, Bc, b_cqk, pc,  256,  768);
    gemm_mma<<<dim3(1152 / 128, NTOK / 128), 256, gsm>>>(Av, Bv, biasv, pv,  768, 1152);

    scatter_k<<<NTOK, 256>>>(gm_vqk, gm_cqk, lam);

    const int asm_ = 81028;
    cudaFuncSetAttribute(attn_k, cudaFuncAttributeMaxDynamicSharedMemorySize, asm_);
    attn_k<<<Bb * NH_ * NW_ * NW_, 256, asm_>>>(pos);

    gemm_mma<<<dim3(384 / 128, NTOK / 128), 256, gsm>>>(Yb, Bo, b_ov, out, 768, 384);
}